// round 6
// baseline (speedup 1.0000x reference)
#include <cuda_runtime.h>

#define FFT_L   8192
#define NLAYERS 4
#define NSTATE  64
#define NROWS   4096
#define THREADS 512

// ---------------- static device scratch ----------------
__device__ __align__(16) float  g_scratch[(size_t)NROWS * FFT_L];   // ping buffer
__device__ __align__(16) float2 g_tw[FFT_L];                        // W_N^k
__device__ __align__(16) float2 g_kraw[NLAYERS][FFT_L];             // raw K(omega_j)
__device__ __align__(16) float2 g_ke[NLAYERS][FFT_L];               // Hermitian kernel * (1/N)

// ---------------- complex helpers ----------------
__device__ __forceinline__ float2 cmul(float2 a, float2 b) {
    return make_float2(fmaf(a.x, b.x, -a.y * b.y), fmaf(a.x, b.y, a.y * b.x));
}
__device__ __forceinline__ float2 cadd(float2 a, float2 b) { return make_float2(a.x + b.x, a.y + b.y); }
__device__ __forceinline__ float2 csub(float2 a, float2 b) { return make_float2(a.x - b.x, a.y - b.y); }
template <bool INV>
__device__ __forceinline__ float2 mulj(float2 a) {   // * (-i) fwd, * (+i) inv
    return INV ? make_float2(-a.y, a.x) : make_float2(a.y, -a.x);
}
__device__ __forceinline__ float gelu_exact(float v) {
    return 0.5f * v * (1.0f + erff(v * 0.70710678118654752f));
}
// pair-level bank swizzle: P indexes 16B pairs (elements 2P, 2P+1)
__device__ __forceinline__ int swp(int P) { return P ^ ((P >> 3) & 7); }
__device__ __forceinline__ float2 ld_elem(const float2* s, int i) {
    return s[(swp(i >> 1) << 1) | (i & 1)];
}
__device__ __forceinline__ void st_elem(float2* s, int i, float2 v) {
    s[(swp(i >> 1) << 1) | (i & 1)] = v;
}
__device__ __forceinline__ float4 pack2(float2 a, float2 b) {
    return make_float4(a.x, a.y, b.x, b.y);
}

// ---------------- DFT-8 / DFT-16 in registers ----------------
template <bool INV>
__device__ __forceinline__ void dft8(float2 a[8]) {
    const float CC = 0.70710678118654752f;
    float2 s0 = cadd(a[0], a[4]), s1 = csub(a[0], a[4]);
    float2 s2 = cadd(a[2], a[6]), s3 = mulj<INV>(csub(a[2], a[6]));
    float2 E0 = cadd(s0, s2), E2 = csub(s0, s2);
    float2 E1 = cadd(s1, s3), E3 = csub(s1, s3);
    float2 t0 = cadd(a[1], a[5]), t1 = csub(a[1], a[5]);
    float2 t2 = cadd(a[3], a[7]), t3 = mulj<INV>(csub(a[3], a[7]));
    float2 O0 = cadd(t0, t2), O2 = csub(t0, t2);
    float2 O1 = cadd(t1, t3), O3 = csub(t1, t3);
    float2 O1w = INV ? make_float2(CC * (O1.x - O1.y), CC * (O1.x + O1.y))
                     : make_float2(CC * (O1.x + O1.y), CC * (O1.y - O1.x));
    float2 O2w = mulj<INV>(O2);
    float2 O3w = INV ? make_float2(-CC * (O3.x + O3.y), CC * (O3.x - O3.y))
                     : make_float2(CC * (O3.y - O3.x), -CC * (O3.x + O3.y));
    a[0] = cadd(E0, O0);  a[4] = csub(E0, O0);
    a[1] = cadd(E1, O1w); a[5] = csub(E1, O1w);
    a[2] = cadd(E2, O2w); a[6] = csub(E2, O2w);
    a[3] = cadd(E3, O3w); a[7] = csub(E3, O3w);
}

template <bool INV>
__device__ __forceinline__ void dft16(const float2 a[16], float2 X[16]) {
    float2 E[8] = {a[0], a[2], a[4], a[6], a[8], a[10], a[12], a[14]};
    float2 O[8] = {a[1], a[3], a[5], a[7], a[9], a[11], a[13], a[15]};
    dft8<INV>(E);
    dft8<INV>(O);
    const float c1 = 0.9238795325112867f, s1 = 0.3826834323650898f,
                SQ = 0.7071067811865476f;
    const float sg = INV ? 1.0f : -1.0f;
    float2 W[8];
    W[0] = make_float2(1.f, 0.f);
    W[1] = make_float2(c1, sg * s1);
    W[2] = make_float2(SQ, sg * SQ);
    W[3] = make_float2(s1, sg * c1);
    W[4] = make_float2(0.f, sg);
    W[5] = make_float2(-s1, sg * c1);
    W[6] = make_float2(-SQ, sg * SQ);
    W[7] = make_float2(-c1, sg * s1);
#pragma unroll
    for (int k = 0; k < 8; ++k) {
        float2 t = cmul(O[k], W[k]);
        X[k]     = cadd(E[k], t);
        X[k + 8] = csub(E[k], t);
    }
}

// ---------------- prologue kernels ----------------
__global__ void init_tw_kernel() {
    int j = blockIdx.x * blockDim.x + threadIdx.x;
    if (j < FFT_L) {
        float s, c;
        sincospif(-(float)j / (float)(FFT_L / 2), &s, &c);
        g_tw[j] = make_float2(c, s);
    }
}

__global__ void compute_k_kernel(const float* __restrict__ Lr, const float* __restrict__ Li,
                                 const float* __restrict__ P,  const float* __restrict__ B,
                                 const float* __restrict__ Ct, const float* __restrict__ step) {
    int gid = blockIdx.x * blockDim.x + threadIdx.x;
    if (gid >= NLAYERS * FFT_L) return;
    int layer = gid >> 13;
    int j     = gid & (FFT_L - 1);
    const float* lr = Lr + layer * NSTATE;
    const float* li = Li + layer * NSTATE;
    const float* Pp = P  + layer * NSTATE;
    const float* Bp = B  + layer * NSTATE;
    const float* Cp = Ct + layer * NSTATE;
    float st = step[layer];

    float ang = (-6.2831855f * (float)j) / 8192.0f;
    float s, c;
    sincosf(ang, &s, &c);
    float opr = 1.0f + c, opi = s;
    float omr = 1.0f - c, omi = -s;
    float inv_p2 = 1.0f / (opr * opr + opi * opi);
    float qr = (omr * opr + omi * opi) * inv_p2;
    float qi = (omi * opr - omr * opi) * inv_p2;
    float gsc = 2.0f / st;
    float gr = gsc * qr, gi = gsc * qi;
    float cr = 2.0f * opr * inv_p2, ci = -2.0f * opi * inv_p2;

    float k00r = 0.f, k00i = 0.f, k01r = 0.f, k01i = 0.f;
    float k10r = 0.f, k10i = 0.f, k11r = 0.f, k11i = 0.f;
#pragma unroll 8
    for (int n = 0; n < NSTATE; n++) {
        float dr = gr - lr[n];
        float di = gi - li[n];
        float inv = 1.0f / (dr * dr + di * di);
        float ir = dr * inv, ii = -di * inv;
        float b = Bp[n], p = Pp[n], ct = Cp[n];
        float v00 = ct * b, v01 = ct * p, v10 = p * b, v11 = p * p;
        k00r += v00 * ir; k00i += v00 * ii;
        k01r += v01 * ir; k01i += v01 * ii;
        k10r += v10 * ir; k10i += v10 * ii;
        k11r += v11 * ir; k11i += v11 * ii;
    }
    float d1r = 1.0f + k11r, d1i = k11i;
    float invd1 = 1.0f / (d1r * d1r + d1i * d1i);
    float numr = k01r * k10r - k01i * k10i;
    float numi = k01r * k10i + k01i * k10r;
    float qr2 = (numr * d1r + numi * d1i) * invd1;
    float qi2 = (numi * d1r - numr * d1i) * invd1;
    float tr = k00r - qr2, ti = k00i - qi2;
    g_kraw[layer][j] = make_float2(cr * tr - ci * ti, cr * ti + ci * tr);
}

__global__ void symmetrize_k_kernel() {
    int gid = blockIdx.x * blockDim.x + threadIdx.x;
    if (gid >= NLAYERS * FFT_L) return;
    int layer = gid >> 13;
    int j     = gid & (FFT_L - 1);
    float2 K1 = g_kraw[layer][j];
    float2 K2 = g_kraw[layer][(FFT_L - j) & (FFT_L - 1)];
    const float sc = 0.5f / (float)FFT_L;   // Hermitian part * 1/N
    g_ke[layer][j] = make_float2((K1.x + K2.x) * sc, (K1.y - K2.y) * sc);
}

// ---------------- stage 1: radix-16 at s=1 (pair float4 stores) ----------------
// a[16] in registers; store dst[16t + k] * W_N^{t*k}
template <bool INV>
__device__ __forceinline__ void stage1_store(float4* __restrict__ dst,
                                             const float2 a[16], int t) {
    float2 X[16];
    dft16<INV>(a, X);
    float2 w1 = g_tw[t];
    if (INV) w1.y = -w1.y;
    // running-product twiddles
    float2 e0 = X[0];
    float2 wk = w1;
    float2 e1 = cmul(X[1], wk);
    dst[swp((t << 3) + 0)] = pack2(e0, e1);
#pragma unroll
    for (int m = 1; m < 8; ++m) {
        wk = cmul(wk, w1);
        float2 pa = cmul(X[2 * m], wk);
        wk = cmul(wk, w1);
        float2 pb = cmul(X[2 * m + 1], wk);
        dst[swp((t << 3) + m)] = pack2(pa, pb);
    }
}

// ---------------- stage 2: radix-16 at s=16 (element smem ops) ----------------
template <bool INV>
__device__ __forceinline__ void stage2(const float2* __restrict__ src,
                                       float2* __restrict__ dst, int t) {
    float2 a[16];
#pragma unroll
    for (int j = 0; j < 16; ++j) a[j] = ld_elem(src, t + (j << 9));
    float2 X[16];
    dft16<INV>(a, X);
    float2 w1 = g_tw[t & ~15];
    if (INV) w1.y = -w1.y;
    int base = (t & 15) + ((t >> 4) << 8);
    st_elem(dst, base, X[0]);
    float2 wk = w1;
    st_elem(dst, base + 16, cmul(X[1], wk));
#pragma unroll
    for (int k = 2; k < 16; ++k) {
        wk = cmul(wk, w1);
        st_elem(dst, base + (k << 4), cmul(X[k], wk));
    }
}

// ---------------- stage 3: radix-32 at s=256, split across a thread pair ----------------
// Computes Xo[k] for this thread's 16 output slots k'=k+16*h at i = qp + 256*k'.
template <bool INV>
__device__ __forceinline__ void stage3_compute(const float2* __restrict__ src,
                                               float2 Xo[16], int qp, int h) {
    float2 a[16];
#pragma unroll
    for (int j = 0; j < 16; ++j) a[j] = ld_elem(src, qp + (h << 8) + (j << 9));
    float2 H[16];
    dft16<INV>(a, H);
    if (h) {
#pragma unroll
        for (int k = 1; k < 16; ++k) {
            float2 w = g_tw[k << 8];          // W32^k
            if (INV) w.y = -w.y;
            H[k] = cmul(H[k], w);
        }
    }
#pragma unroll
    for (int k = 0; k < 16; ++k) {
        float2 r;
        r.x = __shfl_xor_sync(0xffffffffu, H[k].x, 1);
        r.y = __shfl_xor_sync(0xffffffffu, H[k].y, 1);
        // h==0: own=E, recv=W*O -> E + WO ; h==1: own=W*O, recv=E -> E - WO
        Xo[k] = h ? csub(r, H[k]) : cadd(H[k], r);
    }
}

// ---------------- fused per-layer kernel ----------------
__global__ void __launch_bounds__(THREADS, 1)
ssm_layer_kernel(const float* __restrict__ in, float* __restrict__ out, int layer) {
    extern __shared__ float4 smem4[];
    float4* X4 = smem4;             // 4096 pairs, swizzled
    float4* Y4 = smem4 + 4096;      // 4096 pairs, swizzled
    float2* Xe = (float2*)X4;
    float2* Ye = (float2*)Y4;

    size_t row = (size_t)blockIdx.x * 2;
    const float* in0 = in + row * FFT_L;
    const float* in1 = in + (row + 1) * FFT_L;
    int t = threadIdx.x;

    // ---- F1: radix-16 (s=1) straight from gmem ----
    {
        float2 a[16];
#pragma unroll
        for (int j = 0; j < 16; ++j) {
            int i = t + (j << 9);
            a[j] = make_float2(in0[i], in1[i]);   // pack 2 real rows as complex
        }
        stage1_store<false>(X4, a, t);
    }
    __syncthreads();

    // ---- F2: radix-16 (s=16) ----
    stage2<false>(Xe, Ye, t);
    __syncthreads();

    // ---- F3: radix-32 (s=256) + filter, writes natural-order spectrum ----
    {
        int qp = t >> 1, h = t & 1;
        float2 Xo[16];
        stage3_compute<false>(Ye, Xo, qp, h);
        const float2* __restrict__ ke = g_ke[layer];
#pragma unroll
        for (int k = 0; k < 16; ++k) {
            int i = qp + (k << 8) + (h << 12);
            st_elem(Xe, i, cmul(Xo[k], ke[i]));
        }
    }
    __syncthreads();

    // ---- I1: radix-16 (s=1) on the filtered spectrum ----
    {
        float2 a[16];
#pragma unroll
        for (int j = 0; j < 16; ++j) a[j] = ld_elem(Xe, t + (j << 9));
        stage1_store<true>(Y4, a, t);
    }
    __syncthreads();

    // ---- I2: radix-16 (s=16) ----
    stage2<true>(Ye, Xe, t);
    __syncthreads();

    // ---- I3: radix-32 (s=256) + residual (re-read gmem) + GELU -> gmem ----
    {
        int qp = t >> 1, h = t & 1;
        float2 Xo[16];
        stage3_compute<true>(Xe, Xo, qp, h);
        float* o0 = out + row * FFT_L;
        float* o1 = out + (row + 1) * FFT_L;
#pragma unroll
        for (int k = 0; k < 16; ++k) {
            int i = qp + (k << 8) + (h << 12);
            o0[i] = gelu_exact(Xo[k].x + in0[i]);
            o1[i] = gelu_exact(Xo[k].y + in1[i]);
        }
    }
}

// ---------------- launch ----------------
extern "C" void kernel_launch(void* const* d_in, const int* in_sizes, int n_in,
                              void* d_out, int out_size) {
    const float* u  = (const float*)d_in[0];
    const float* Lr = (const float*)d_in[1];
    const float* Li = (const float*)d_in[2];
    const float* P  = (const float*)d_in[3];
    const float* B  = (const float*)d_in[4];
    const float* Ct = (const float*)d_in[5];
    const float* st = (const float*)d_in[6];
    float* out = (float*)d_out;

    float* scratch = nullptr;
    cudaGetSymbolAddress((void**)&scratch, g_scratch);

    const size_t smem_bytes = 2 * 4096 * sizeof(float4);   // 128 KB
    cudaFuncSetAttribute(ssm_layer_kernel,
                         cudaFuncAttributeMaxDynamicSharedMemorySize, (int)smem_bytes);

    init_tw_kernel<<<FFT_L / 256, 256>>>();
    compute_k_kernel<<<(NLAYERS * FFT_L) / 256, 256>>>(Lr, Li, P, B, Ct, st);
    symmetrize_k_kernel<<<(NLAYERS * FFT_L) / 256, 256>>>();

    ssm_layer_kernel<<<NROWS / 2, THREADS, smem_bytes>>>(u,       scratch, 0);
    ssm_layer_kernel<<<NROWS / 2, THREADS, smem_bytes>>>(scratch, out,     1);
    ssm_layer_kernel<<<NROWS / 2, THREADS, smem_bytes>>>(out,     scratch, 2);
    ssm_layer_kernel<<<NROWS / 2, THREADS, smem_bytes>>>(scratch, out,     3);
}